// round 8
// baseline (speedup 1.0000x reference)
#include <cuda_runtime.h>
#include <cuda_bf16.h>
#include <cstdint>

// Problem constants
constexpr int Dd   = 256;       // latent dim
constexpr int HW   = 4096;      // 64*64
constexpr int NPIX = 65536;     // 16*64*64
constexpr int KK   = 1024;      // codebook size
constexpr int NOUT = 16777216;  // 16*256*64*64

// ---------------------------------------------------------------------------
// Scratch (static device globals; no allocations allowed)
__device__ float g_t2[KK];
__device__ int   g_idx[NPIX];
__device__ float g_part[NPIX / 32];

// B split levels, bf16: [level][k][256]
__device__ unsigned short g_b[2][(size_t)KK * Dd];

// ---------------------------------------------------------------------------
// PTX helpers (arch-agnostic sm_80+ ISA only)
__device__ __forceinline__ uint32_t smem_u32(const void* p) {
    uint32_t a;
    asm("{ .reg .u64 t; cvta.to.shared.u64 t, %1; cvt.u32.u64 %0, t; }" : "=r"(a) : "l"(p));
    return a;
}
__device__ __forceinline__ void ldsm4(uint32_t addr, unsigned& r0, unsigned& r1,
                                      unsigned& r2, unsigned& r3) {
    asm volatile("ldmatrix.sync.aligned.m8n8.x4.shared.b16 {%0,%1,%2,%3}, [%4];"
        : "=r"(r0), "=r"(r1), "=r"(r2), "=r"(r3) : "r"(addr));
}
__device__ __forceinline__ void mma16816(float* d, const unsigned* a, const unsigned* b) {
    asm volatile("mma.sync.aligned.m16n8k16.row.col.f32.bf16.bf16.f32 "
        "{%0,%1,%2,%3}, {%4,%5,%6,%7}, {%8,%9}, {%0,%1,%2,%3};"
        : "+f"(d[0]), "+f"(d[1]), "+f"(d[2]), "+f"(d[3])
        : "r"(a[0]), "r"(a[1]), "r"(a[2]), "r"(a[3]), "r"(b[0]), "r"(b[1]));
}
__device__ __forceinline__ void cp16(uint32_t dst, const void* src) {
    asm volatile("cp.async.cg.shared.global [%0], [%1], 16;" :: "r"(dst), "l"(src));
}
#define CP_COMMIT() asm volatile("cp.async.commit_group;" ::: "memory")

// ---------------------------------------------------------------------------
// ||e_k||^2 (fp64-accumulated, rounded to f32)
__global__ void t2_kernel(const float* __restrict__ emb) {
    int k = blockIdx.x * blockDim.x + threadIdx.x;
    if (k < KK) {
        const float* row = emb + (size_t)k * Dd;
        double s = 0.0;
        #pragma unroll 8
        for (int d = 0; d < Dd; d++) { double v = (double)row[d]; s += v * v; }
        g_t2[k] = (float)s;
    }
}

// ---------------------------------------------------------------------------
__device__ __forceinline__ void split2(float v, unsigned short& s0, unsigned short& s1) {
    __nv_bfloat16 b0 = __float2bfloat16_rn(v);
    float r = v - __bfloat162float(b0);
    __nv_bfloat16 b1 = __float2bfloat16_rn(r);
    s0 = __bfloat16_as_ushort(b0);
    s1 = __bfloat16_as_ushort(b1);
}

// B prep: elementwise split of emb into 2 bf16 levels
__global__ void prep_b_kernel(const float* __restrict__ emb) {
    int i = blockIdx.x * blockDim.x + threadIdx.x;
    float v = emb[i];
    unsigned short s0, s1;
    split2(v, s0, s1);
    g_b[0][i] = s0;
    g_b[1][i] = s1;
}

// ---------------------------------------------------------------------------
// Fused A-prep + split-GEMM + argmin on HMMA.
// CTA: 128 pixels x 1024 codes. 8 warps, grid 2(m) x 4(n), warp tile 64x64.
// A (2 bf16 levels) built in-kernel from z (split2 + fp64 t1, bit-identical to
// the old prep_a), resident in SMEM (528B rows, conflict-free ldmatrix).
// B chunks: 256 codes x 32 k, both levels (row = 64B lev0 | 64B lev1 | 16B pad),
// double-buffered cp.async, ONE barrier per chunk.
constexpr int AS_LEV   = 128 * 528;            // 67584
constexpr int BS_OFF   = 2 * AS_LEV;           // 135168
constexpr int BS_BUF   = 256 * 144;            // 36864
constexpr int T2_OFF   = BS_OFF + 2 * BS_BUF;  // 208896
constexpr int T1_OFF   = T2_OFF + 4096;        // 212992
constexpr int REDV_OFF = T1_OFF + 512;         // 213504
constexpr int REDK_OFF = REDV_OFF + 2048;      // 215552
constexpr int SM_TOTAL = REDK_OFF + 2048;      // 217600

constexpr int NCHUNK = 32;  // 4 cb (256 codes) x 8 kc (32 k)

__global__ __launch_bounds__(256, 1)
void argmin_mma_kernel(const float* __restrict__ z) {
    extern __shared__ char smem[];
    const uint32_t sbase = smem_u32(smem);
    const int tid   = threadIdx.x;
    const int lane  = tid & 31;
    const int wid   = tid >> 5;
    const int wm    = wid >> 2;          // 0..1
    const int wn    = wid & 3;           // 0..3
    const int m0    = blockIdx.x * 128;
    const int b     = m0 >> 12;
    const int hw0   = m0 & 4095;

    // t2 -> smem
    #pragma unroll
    for (int i = 0; i < 4; i++)
        ((float*)(smem + T2_OFF))[tid + i * 256] = g_t2[tid + i * 256];

    // ---- Fused A prep: z slice -> split2 -> A smem; fp64 t1 (prep_a-identical) ----
    {
        float* stage = (float*)(smem + BS_OFF);   // 32 x 128 f32 staging (16KB)
        const float* zb = z + (size_t)b * (size_t)(Dd * HW) + hw0;
        const int pl = tid & 127;
        const int h  = tid >> 7;                  // 0/1
        double t1acc = 0.0;

        for (int d0 = 0; d0 < Dd; d0 += 32) {
            __syncthreads();
            #pragma unroll
            for (int r = 0; r < 16; r++) {
                int e = tid + r * 256;
                int dl = e >> 7, hwi = e & 127;
                stage[dl * 128 + hwi] = zb[(size_t)(d0 + dl) * HW + hwi];
            }
            __syncthreads();
            #pragma unroll
            for (int u = 0; u < 8; u++) {
                int dp = h * 8 + u;
                float f0 = stage[(2 * dp) * 128 + pl];
                float f1 = stage[(2 * dp + 1) * 128 + pl];
                t1acc += (double)f0 * f0 + (double)f1 * f1;
                unsigned short a0, a1, c0, c1;
                split2(f0, a0, a1);
                split2(f1, c0, c1);
                int col = (d0 >> 1) + h * 8 + u;
                *(unsigned*)(smem + 0 * AS_LEV + pl * 528 + col * 4) =
                    (unsigned)a0 | ((unsigned)c0 << 16);
                *(unsigned*)(smem + 1 * AS_LEV + pl * 528 + col * 4) =
                    (unsigned)a1 | ((unsigned)c1 << 16);
            }
        }
        double* t1p = (double*)(smem + REDV_OFF);  // red region free until end
        t1p[h * 128 + pl] = t1acc;
        __syncthreads();
        if (tid < 128)
            ((float*)(smem + T1_OFF))[tid] = (float)(t1p[tid] + t1p[128 + tid]);
    }

    // lane-dependent ldmatrix offsets
    const int g = lane >> 2;
    const int a_kadd = (lane >> 4) * 8;                // k elems
    const int b_kadd = ((lane >> 3) & 1) * 8;          // k elems
    uint32_t aRow[4], bRow[4];
    #pragma unroll
    for (int im = 0; im < 4; im++)
        aRow[im] = (uint32_t)((wm * 64 + im * 16 + (lane & 7) + ((lane >> 3) & 1) * 8) * 528);
    #pragma unroll
    for (int j2 = 0; j2 < 4; j2++)
        bRow[j2] = (uint32_t)((wn * 64 + j2 * 16 + (lane & 7) + ((lane >> 4) & 1) * 8) * 144);

    float acc[4][8][4];
    #pragma unroll
    for (int im = 0; im < 4; im++)
        #pragma unroll
        for (int jn = 0; jn < 8; jn++)
            #pragma unroll
            for (int c = 0; c < 4; c++) acc[im][jn][c] = 0.0f;

    float bestv[8];
    int   bestk[8];
    #pragma unroll
    for (int r = 0; r < 8; r++) { bestv[r] = 3.4e38f; bestk[r] = 0; }

    // chunk i -> cb = i>>3 (256-code block), kc = i&7 (32-k slab).
    auto issue = [&](int i) {
        int cb = i >> 3, kc = i & 7;
        uint32_t dstbase = sbase + BS_OFF + (uint32_t)(i & 1) * BS_BUF;
        #pragma unroll
        for (int j = 0; j < 8; j++) {
            int f = j * 256 + tid;         // 0..2047
            int n = f >> 3, seg = f & 7;
            int lev = seg >> 2, kq = seg & 3;
            const char* src = (const char*)&g_b[lev][((size_t)(cb * 256 + n)) * Dd + kc * 32]
                            + kq * 16;
            cp16(dstbase + (uint32_t)n * 144 + seg * 16, src);
        }
        CP_COMMIT();
    };

    __syncthreads();       // A smem + t1 visible to all before mainloop
    issue(0);

    for (int i = 0; i < NCHUNK; i++) {
        asm volatile("cp.async.wait_group 0;" ::: "memory");
        __syncthreads();   // chunk i data ready; all warps done reading buf (i+1)&1
        if (i + 1 < NCHUNK) issue(i + 1);

        const int cb = i >> 3, kc = i & 7;
        const uint32_t Bbase = sbase + BS_OFF + (uint32_t)(i & 1) * BS_BUF;

        #pragma unroll
        for (int s = 0; s < 2; s++) {      // two k16 slabs in the k32 chunk
            const int kglob = kc * 32 + s * 16;
            unsigned af0[4][4], af1[4][4], bf0[8][2], bf1[8][2];
            #pragma unroll
            for (int im = 0; im < 4; im++)
                ldsm4(sbase + aRow[im] + (uint32_t)(kglob + a_kadd) * 2,
                      af0[im][0], af0[im][1], af0[im][2], af0[im][3]);
            #pragma unroll
            for (int j2 = 0; j2 < 4; j2++) {
                unsigned r0, r1, r2, r3;
                ldsm4(Bbase + bRow[j2] + (uint32_t)(s * 32 + b_kadd * 2), r0, r1, r2, r3);
                bf0[j2 * 2][0] = r0;     bf0[j2 * 2][1] = r1;
                bf0[j2 * 2 + 1][0] = r2; bf0[j2 * 2 + 1][1] = r3;
            }
            #pragma unroll
            for (int im = 0; im < 4; im++)
                ldsm4(sbase + AS_LEV + aRow[im] + (uint32_t)(kglob + a_kadd) * 2,
                      af1[im][0], af1[im][1], af1[im][2], af1[im][3]);
            #pragma unroll
            for (int j2 = 0; j2 < 4; j2++) {
                unsigned r0, r1, r2, r3;
                ldsm4(Bbase + bRow[j2] + (uint32_t)(64 + s * 32 + b_kadd * 2), r0, r1, r2, r3);
                bf1[j2 * 2][0] = r0;     bf1[j2 * 2][1] = r1;
                bf1[j2 * 2 + 1][0] = r2; bf1[j2 * 2 + 1][1] = r3;
            }
            // Product-major passes: 32 independent MMAs per pass, no dependent
            // back-to-back issues. Per-accumulator order (A0B0, A1B0, A0B1)
            // unchanged -> bit-identical to previous rounds.
            #pragma unroll
            for (int im = 0; im < 4; im++)
                #pragma unroll
                for (int jn = 0; jn < 8; jn++)
                    mma16816(acc[im][jn], af0[im], bf0[jn]);
            #pragma unroll
            for (int im = 0; im < 4; im++)
                #pragma unroll
                for (int jn = 0; jn < 8; jn++)
                    mma16816(acc[im][jn], af1[im], bf0[jn]);
            #pragma unroll
            for (int im = 0; im < 4; im++)
                #pragma unroll
                for (int jn = 0; jn < 8; jn++)
                    mma16816(acc[im][jn], af0[im], bf1[jn]);
        }

        if (kc == 7) {
            // epilogue for code block cb: bit-faithful score + per-row argmin
            const float* t2s = (const float*)(smem + T2_OFF);
            const float* t1s = (const float*)(smem + T1_OFF);
            #pragma unroll
            for (int im = 0; im < 4; im++) {
                float t1a = t1s[wm * 64 + im * 16 + g];
                float t1b = t1s[wm * 64 + im * 16 + g + 8];
                #pragma unroll
                for (int jn = 0; jn < 8; jn++) {
                    int kbase = cb * 256 + wn * 64 + jn * 8 + (lane & 3) * 2;
                    float t2a = t2s[kbase], t2b = t2s[kbase + 1];
                    float d0v = __fadd_rn(__fadd_rn(t1a, t2a), -2.0f * acc[im][jn][0]);
                    float d1v = __fadd_rn(__fadd_rn(t1a, t2b), -2.0f * acc[im][jn][1]);
                    if (d0v < bestv[im * 2]) { bestv[im * 2] = d0v; bestk[im * 2] = kbase; }
                    if (d1v < bestv[im * 2]) { bestv[im * 2] = d1v; bestk[im * 2] = kbase + 1; }
                    float d2v = __fadd_rn(__fadd_rn(t1b, t2a), -2.0f * acc[im][jn][2]);
                    float d3v = __fadd_rn(__fadd_rn(t1b, t2b), -2.0f * acc[im][jn][3]);
                    if (d2v < bestv[im * 2 + 1]) { bestv[im * 2 + 1] = d2v; bestk[im * 2 + 1] = kbase; }
                    if (d3v < bestv[im * 2 + 1]) { bestv[im * 2 + 1] = d3v; bestk[im * 2 + 1] = kbase + 1; }
                    #pragma unroll
                    for (int c = 0; c < 4; c++) acc[im][jn][c] = 0.0f;
                }
            }
        }
    }

    // quad reduction (lanes in same group of 4 hold same rows, different cols)
    #pragma unroll
    for (int off = 1; off <= 2; off <<= 1) {
        #pragma unroll
        for (int r = 0; r < 8; r++) {
            float ov = __shfl_xor_sync(0xffffffffu, bestv[r], off);
            int   ok = __shfl_xor_sync(0xffffffffu, bestk[r], off);
            if (ov < bestv[r] || (ov == bestv[r] && ok < bestk[r])) {
                bestv[r] = ov; bestk[r] = ok;
            }
        }
    }
    float* redv = (float*)(smem + REDV_OFF);
    int*   redk = (int*)(smem + REDK_OFF);
    __syncthreads();   // t1p (double) staging in REDV region fully consumed long ago
    if ((lane & 3) == 0) {
        #pragma unroll
        for (int im = 0; im < 4; im++) {
            #pragma unroll
            for (int hh = 0; hh < 2; hh++) {
                int row = wm * 64 + im * 16 + g + hh * 8;
                redv[row * 4 + wn] = bestv[im * 2 + hh];
                redk[row * 4 + wn] = bestk[im * 2 + hh];
            }
        }
    }
    __syncthreads();
    if (tid < 128) {
        float bv = redv[tid * 4];
        int   bk = redk[tid * 4];
        #pragma unroll
        for (int w = 1; w < 4; w++) {
            float v = redv[tid * 4 + w];
            int   k = redk[tid * 4 + w];
            if (v < bv || (v == bv && k < bk)) { bv = v; bk = k; }
        }
        g_idx[m0 + tid] = bk;
    }
}

// ---------------------------------------------------------------------------
// Gather z_q = emb[idx], write NCHW output, loss partials, indices as float.
__global__ void out_kernel(const float* __restrict__ z, const float* __restrict__ emb,
                           float* __restrict__ out, float* __restrict__ idx_out,
                           int has_idx) {
    __shared__ int   sidx[32];
    __shared__ float red[256];
    const int tid = threadIdx.x;
    const int p0  = blockIdx.x * 32;
    const int b   = p0 >> 12;
    const int hw0 = p0 & 4095;

    if (tid < 32) {
        int iv = g_idx[p0 + tid];
        sidx[tid] = iv;
        if (has_idx) idx_out[p0 + tid] = (float)iv;
    }
    __syncthreads();

    const int p  = tid & 31;
    const int dl = tid >> 5;
    const float* zb   = z   + (size_t)b * (size_t)(Dd * HW) + hw0 + p;
    float*       ob   = out + (size_t)b * (size_t)(Dd * HW) + hw0 + p;
    const float* erow = emb + (size_t)sidx[p] * Dd;

    float acc = 0.0f;
    #pragma unroll
    for (int db = 0; db < 32; db++) {
        int d = db * 8 + dl;
        float e  = erow[d];
        float zv = zb[(size_t)d * HW];
        ob[(size_t)d * HW] = e;
        float df = e - zv;
        acc = fmaf(df, df, acc);
    }

    red[tid] = acc;
    __syncthreads();
    for (int s = 128; s > 0; s >>= 1) {
        if (tid < s) red[tid] += red[tid + s];
        __syncthreads();
    }
    if (tid == 0) g_part[blockIdx.x] = red[0];
}

__global__ void loss_kernel(float* __restrict__ out_loss) {
    __shared__ double red[256];
    const int tid = threadIdx.x;
    double s = 0.0;
    #pragma unroll
    for (int i = 0; i < 8; i++) s += (double)g_part[tid * 8 + i];
    red[tid] = s;
    __syncthreads();
    for (int st = 128; st > 0; st >>= 1) {
        if (tid < st) red[tid] += red[tid + st];
        __syncthreads();
    }
    if (tid == 0) *out_loss = (float)(0.25 * (red[0] / (double)NOUT));
}

// ---------------------------------------------------------------------------
extern "C" void kernel_launch(void* const* d_in, const int* in_sizes, int n_in,
                              void* d_out, int out_size) {
    const float* z   = (const float*)d_in[0];
    const float* emb = (const float*)d_in[1];
    float* out = (float*)d_out;

    const int has_idx  = (out_size >= NOUT + NPIX) ? 1 : 0;
    const int has_loss = (out_size >= NOUT + NPIX + 1) ? 1 : 0;

    static int attr_done = 0;
    if (!attr_done) {
        cudaFuncSetAttribute(argmin_mma_kernel,
                             cudaFuncAttributeMaxDynamicSharedMemorySize, SM_TOTAL);
        attr_done = 1;
    }

    prep_b_kernel<<<KK * Dd / 256, 256>>>(emb);
    t2_kernel<<<KK / 256, 256>>>(emb);
    argmin_mma_kernel<<<512, 256, SM_TOTAL>>>(z);
    out_kernel<<<NPIX / 32, 256>>>(z, emb, out, out + NOUT, has_idx);
    if (has_loss) loss_kernel<<<1, 256>>>(out + NOUT + NPIX);
}